// round 1
// baseline (speedup 1.0000x reference)
#include <cuda_runtime.h>
#include <cuda_bf16.h>
#include <math.h>

// Problem constants
#define BB    16
#define CIN   128
#define COUT  256
#define HH    80
#define WW    80
#define KK9   9
#define HO    40
#define WO    40
#define NP    (HO*WO)        // 1600
#define RED   (CIN*KK9)      // 1152
#define TP    16             // positions per block in main kernel
#define CC    16             // channel chunk in main kernel
#define SSTRIDE 148          // padded stride (floats) per channel in ssamp

// ---------------- scratch (static device arrays; no allocation) ----------------
__device__ float  g_xT[BB*HH*WW*CIN];        // [b][y][x][c]   52.4 MB
__device__ float  g_wT[RED*COUT];            // [(c*9+k)][o]    1.2 MB
__device__ float4 g_params[BB*NP*KK9];       // per (b,p,k): {y0,x0,wy1,wx1}
__device__ float  g_pre[BB*COUT*NP];         // conv output pre-BN  26.2 MB
__device__ float  g_bn[2*COUT];              // scale, shift per channel

// ---------------- f32x2 helpers ----------------
__device__ __forceinline__ unsigned long long pk2(float lo, float hi) {
    unsigned long long r;
    asm("mov.b64 %0, {%1, %2};" : "=l"(r) : "f"(lo), "f"(hi));
    return r;
}
__device__ __forceinline__ void upk2(unsigned long long v, float& lo, float& hi) {
    asm("mov.b64 {%0, %1}, %2;" : "=f"(lo), "=f"(hi) : "l"(v));
}
__device__ __forceinline__ void fma2(unsigned long long& d, unsigned long long a, unsigned long long b) {
    asm("fma.rn.f32x2 %0, %1, %2, %0;" : "+l"(d) : "l"(a), "l"(b));
}

// ---------------- K0: transpose x (B,C,H,W) -> xT (B,H,W,C) ----------------
__global__ void k_transpose(const float* __restrict__ x) {
    int b = blockIdx.x / HH;
    int y = blockIdx.x % HH;
    int c = threadIdx.x;                       // 128 threads
    const float* src = x + (((size_t)(b*CIN + c))*HH + y)*WW;
    float* dst = &g_xT[((size_t)(b*HH + y))*WW*CIN + c];
    #pragma unroll 4
    for (int xx = 0; xx < WW; xx++) {
        dst[(size_t)xx*CIN] = src[xx];
    }
}

// ---------------- K0b: transpose weights (O, C*9) -> (C*9, O) ----------------
__global__ void k_wt(const float* __restrict__ w) {
    int i = blockIdx.x*256 + threadIdx.x;
    if (i < RED*COUT) {
        int ck = i / COUT;
        int o  = i % COUT;
        g_wT[i] = w[(size_t)o*RED + ck];
    }
}

// ---------------- K1: offsets + bilinear params ----------------
// One warp per output position. 18-wide 1x1 conv over 128 channels, then
// per-tap (k=lane<9) floor/frac decomposition.
__global__ void k_offsets(const float* __restrict__ offw, const float* __restrict__ offb) {
    int gw   = (blockIdx.x * blockDim.x + threadIdx.x) >> 5;  // global warp id
    int lane = threadIdx.x & 31;
    if (gw >= BB*NP) return;
    int b = gw / NP, p = gw % NP;
    int ho = p / WO, wo = p % WO;

    const float4* xs = (const float4*)&g_xT[(((size_t)b*HH + 2*ho)*WW + 2*wo)*CIN];
    float4 xv = xs[lane];                      // channels 4*lane .. 4*lane+3

    float dy = 0.f, dx = 0.f;
    #pragma unroll
    for (int j = 0; j < 18; j++) {
        const float* wr = offw + j*CIN + lane*4;
        float s = wr[0]*xv.x + wr[1]*xv.y + wr[2]*xv.z + wr[3]*xv.w;
        #pragma unroll
        for (int d = 16; d > 0; d >>= 1) s += __shfl_xor_sync(0xffffffffu, s, d);
        if (lane < 9) {
            if (j == 2*lane)     dy = s;
            if (j == 2*lane + 1) dx = s;
        }
    }
    if (lane < 9) {
        int k = lane;
        dy += __ldg(&offb[2*k]);
        dx += __ldg(&offb[2*k+1]);
        float py = (float)(ho*2 - 1 + k/3) + dy;
        float px = (float)(wo*2 - 1 + k%3) + dx;
        float fy = floorf(py), fx = floorf(px);
        int y0 = (int)fy, x0 = (int)fx;
        g_params[(size_t)gw*KK9 + k] =
            make_float4(__int_as_float(y0), __int_as_float(x0), py - fy, px - fx);
    }
}

// ---------------- K2: main deformable conv ----------------
// grid = 1600 blocks (b, 16-position tile); 256 threads = one output channel each.
// Accumulators: 16 positions packed as 8 f32x2.
__global__ __launch_bounds__(256) void k_main(const float* __restrict__ deform_b) {
    int bid = blockIdx.x;
    int b   = bid / (NP/TP);
    int p0  = (bid % (NP/TP)) * TP;
    int tid = threadIdx.x;
    int o   = tid;

    __shared__ __align__(16) float4 sp[TP*KK9];          // 144 taps
    __shared__ __align__(16) float  ssamp[CC*SSTRIDE];   // [c][k*16+p], padded

    if (tid < TP*KK9) sp[tid] = g_params[((size_t)b*NP + p0)*KK9 + tid];
    __syncthreads();

    unsigned long long acc[8];
    #pragma unroll
    for (int i = 0; i < 8; i++) acc[i] = 0ULL;

    const float* xb = &g_xT[(size_t)b*HH*WW*CIN];
    int cl  = tid & 15;        // local channel within chunk
    int pkb = tid >> 4;        // base (p,k) index

    #pragma unroll 1
    for (int ch = 0; ch < CIN/CC; ch++) {
        int cglob = ch*CC + cl;
        // ---- fill sampled chunk ----
        #pragma unroll
        for (int it = 0; it < 9; it++) {
            int pk = pkb + it*16;              // 0..143
            int pp = pk / KK9;
            int k  = pk - pp*KK9;
            float4 pr = sp[pk];
            int y0 = __float_as_int(pr.x);
            int x0 = __float_as_int(pr.y);
            float wy1 = pr.z, wx1 = pr.w;
            float wy0 = 1.f - wy1, wx0 = 1.f - wx1;
            int y1 = y0 + 1, x1 = x0 + 1;
            bool vy0 = ((unsigned)y0 < (unsigned)HH);
            bool vy1 = ((unsigned)y1 < (unsigned)HH);
            bool vx0 = ((unsigned)x0 < (unsigned)WW);
            bool vx1 = ((unsigned)x1 < (unsigned)WW);
            int yc0 = min(max(y0, 0), HH-1), yc1 = min(max(y1, 0), HH-1);
            int xc0 = min(max(x0, 0), WW-1), xc1 = min(max(x1, 0), WW-1);
            float g00 = (vy0 && vx0) ? __ldg(xb + ((size_t)yc0*WW + xc0)*CIN + cglob) : 0.f;
            float g01 = (vy0 && vx1) ? __ldg(xb + ((size_t)yc0*WW + xc1)*CIN + cglob) : 0.f;
            float g10 = (vy1 && vx0) ? __ldg(xb + ((size_t)yc1*WW + xc0)*CIN + cglob) : 0.f;
            float g11 = (vy1 && vx1) ? __ldg(xb + ((size_t)yc1*WW + xc1)*CIN + cglob) : 0.f;
            ssamp[cl*SSTRIDE + k*TP + pp] =
                wy0*(wx0*g00 + wx1*g01) + wy1*(wx0*g10 + wx1*g11);
        }
        __syncthreads();

        // ---- GEMM fragment: 16 channels x 9 taps x 16 positions ----
        const float* wp = &g_wT[(size_t)(ch*CC)*KK9*COUT + o];
        #pragma unroll 4
        for (int c = 0; c < CC; c++) {
            #pragma unroll
            for (int k = 0; k < KK9; k++) {
                float w = __ldg(wp + (size_t)(c*KK9 + k)*COUT);
                unsigned long long ww = pk2(w, w);
                const ulonglong2* s2 = (const ulonglong2*)&ssamp[c*SSTRIDE + k*TP];
                ulonglong2 q0 = s2[0], q1 = s2[1];
                fma2(acc[0], ww, q0.x);
                fma2(acc[1], ww, q0.y);
                fma2(acc[2], ww, q1.x);
                fma2(acc[3], ww, q1.y);
                ulonglong2 q2 = s2[2], q3 = s2[3];
                fma2(acc[4], ww, q2.x);
                fma2(acc[5], ww, q2.y);
                fma2(acc[6], ww, q3.x);
                fma2(acc[7], ww, q3.y);
            }
        }
        __syncthreads();
    }

    // ---- epilogue: bias + store 16 consecutive positions ----
    float bias = __ldg(&deform_b[o]);
    float res[16];
    #pragma unroll
    for (int i = 0; i < 8; i++) {
        float lo, hi;
        upk2(acc[i], lo, hi);
        res[2*i]   = lo + bias;
        res[2*i+1] = hi + bias;
    }
    float4* outp = (float4*)&g_pre[((size_t)(b*COUT + o))*NP + p0];
    #pragma unroll
    for (int i = 0; i < 4; i++)
        outp[i] = make_float4(res[4*i], res[4*i+1], res[4*i+2], res[4*i+3]);
}

// ---------------- K3: BN statistics (deterministic two-pass) ----------------
__global__ void k_bnstats(const float* __restrict__ gamma, const float* __restrict__ beta) {
    int o = blockIdx.x;
    int tid = threadIdx.x;
    double s = 0.0, s2 = 0.0;
    for (int b = 0; b < BB; b++) {
        const float* r = &g_pre[((size_t)(b*COUT + o))*NP];
        for (int i = tid; i < NP; i += 256) {
            double v = (double)r[i];
            s  += v;
            s2 += v*v;
        }
    }
    __shared__ double sh[256], sh2[256];
    sh[tid] = s; sh2[tid] = s2;
    __syncthreads();
    for (int d = 128; d > 0; d >>= 1) {
        if (tid < d) { sh[tid] += sh[tid+d]; sh2[tid] += sh2[tid+d]; }
        __syncthreads();
    }
    if (tid == 0) {
        const double N = (double)(BB*NP);
        double mean = sh[0] / N;
        double var  = sh2[0] / N - mean*mean;
        double inv  = 1.0 / sqrt(var + 1e-5);
        float scale = (float)((double)gamma[o] * inv);
        float shift = (float)((double)beta[o] - mean * (double)scale);
        g_bn[2*o]   = scale;
        g_bn[2*o+1] = shift;
    }
}

// ---------------- K4: fused BN + SiLU ----------------
__global__ void k_act(float* __restrict__ out) {
    int i = blockIdx.x*256 + threadIdx.x;      // float4 index
    const int NV = BB*COUT*NP/4;
    if (i >= NV) return;
    int e = i*4;
    int o = (e / NP) & (COUT-1);
    float sc = g_bn[2*o], sh = g_bn[2*o+1];
    float4 v = ((const float4*)g_pre)[i];
    float y0 = v.x*sc + sh;
    float y1 = v.y*sc + sh;
    float y2 = v.z*sc + sh;
    float y3 = v.w*sc + sh;
    v.x = y0 / (1.f + expf(-y0));
    v.y = y1 / (1.f + expf(-y1));
    v.z = y2 / (1.f + expf(-y2));
    v.w = y3 / (1.f + expf(-y3));
    ((float4*)out)[i] = v;
}

// ---------------- launch ----------------
extern "C" void kernel_launch(void* const* d_in, const int* in_sizes, int n_in,
                              void* d_out, int out_size) {
    const float* x        = (const float*)d_in[0];
    const float* offset_w = (const float*)d_in[1];
    const float* offset_b = (const float*)d_in[2];
    const float* deform_w = (const float*)d_in[3];
    const float* deform_b = (const float*)d_in[4];
    const float* bn_gamma = (const float*)d_in[5];
    const float* bn_beta  = (const float*)d_in[6];
    float* out = (float*)d_out;

    k_transpose<<<BB*HH, CIN>>>(x);
    k_wt<<<(RED*COUT + 255)/256, 256>>>(deform_w);
    k_offsets<<<(BB*NP*32 + 127)/128, 128>>>(offset_w, offset_b);
    k_main<<<BB*(NP/TP), 256>>>(deform_b);
    k_bnstats<<<COUT, 256>>>(bn_gamma, bn_beta);
    k_act<<<(BB*COUT*NP/4 + 255)/256, 256>>>(out);
}

// round 2
// speedup vs baseline: 1.4480x; 1.4480x over previous
#include <cuda_runtime.h>
#include <cuda_bf16.h>
#include <math.h>

// Problem constants
#define BB    16
#define CIN   128
#define COUT  256
#define HH    80
#define WW    80
#define KK9   9
#define HO    40
#define WO    40
#define NP    (HO*WO)        // 1600
#define RED   (CIN*KK9)      // 1152
#define TPm   32             // positions per block (k_main)
#define CCm   32             // channels per chunk (k_main)
#define PS    36             // padded row stride (floats) in ssamp

// ---------------- scratch (static device arrays; no allocation) ----------------
__device__ float  g_xT[BB*HH*WW*CIN];        // [b][y][x][c]   52.4 MB
__device__ float  g_wT[RED*COUT];            // [(c*9+k)][o]    1.2 MB
__device__ float4 g_params[BB*NP*KK9];       // per (b,p,k): {y0,x0,wy1,wx1}
__device__ float  g_pre[BB*COUT*NP];         // conv output pre-BN  26.2 MB
__device__ float  g_bn[2*COUT];              // scale, shift per channel

// ---------------- f32x2 helpers ----------------
__device__ __forceinline__ unsigned long long pk2(float lo, float hi) {
    unsigned long long r;
    asm("mov.b64 %0, {%1, %2};" : "=l"(r) : "f"(lo), "f"(hi));
    return r;
}
__device__ __forceinline__ void upk2(unsigned long long v, float& lo, float& hi) {
    asm("mov.b64 {%0, %1}, %2;" : "=f"(lo), "=f"(hi) : "l"(v));
}
__device__ __forceinline__ void fma2(unsigned long long& d, unsigned long long a, unsigned long long b) {
    asm("fma.rn.f32x2 %0, %1, %2, %0;" : "+l"(d) : "l"(a), "l"(b));
}

// ---------------- K0: tiled transpose x (B,C,H,W) -> xT (B,H,W,C) ----------------
// One block per (b, y). Coalesced loads along W, coalesced stores along C.
__global__ __launch_bounds__(256) void k_transpose(const float* __restrict__ x) {
    int b = blockIdx.x / HH;
    int y = blockIdx.x % HH;
    __shared__ float s[CIN*81];                       // 81-pad kills LDS conflicts
    const float* src = x + ((size_t)b*CIN)*HH*WW + (size_t)y*WW;
    int tid = threadIdx.x;
    for (int i = tid; i < CIN*WW; i += 256) {
        int c = i / WW;
        int w = i - c*WW;
        s[c*81 + w] = src[(size_t)c*HH*WW + w];       // per-c rows: coalesced along w
    }
    __syncthreads();
    float* dst = &g_xT[((size_t)(b*HH + y))*WW*CIN];
    for (int i = tid; i < WW*CIN; i += 256) {
        int c = i & (CIN-1);
        int w = i >> 7;
        dst[(size_t)w*CIN + c] = s[c*81 + w];         // coalesced along c
    }
}

// ---------------- K0b: transpose weights (O, C*9) -> (C*9, O) ----------------
__global__ void k_wt(const float* __restrict__ w) {
    int i = blockIdx.x*256 + threadIdx.x;
    if (i < RED*COUT) {
        int ck = i / COUT;
        int o  = i % COUT;
        g_wT[i] = w[(size_t)o*RED + ck];
    }
}

// ---------------- K1: offsets + bilinear params ----------------
__global__ void k_offsets(const float* __restrict__ offw, const float* __restrict__ offb) {
    int gw   = (blockIdx.x * blockDim.x + threadIdx.x) >> 5;
    int lane = threadIdx.x & 31;
    if (gw >= BB*NP) return;
    int b = gw / NP, p = gw % NP;
    int ho = p / WO, wo = p % WO;

    const float4* xs = (const float4*)&g_xT[(((size_t)b*HH + 2*ho)*WW + 2*wo)*CIN];
    float4 xv = xs[lane];

    float dy = 0.f, dx = 0.f;
    #pragma unroll
    for (int j = 0; j < 18; j++) {
        const float* wr = offw + j*CIN + lane*4;
        float s = wr[0]*xv.x + wr[1]*xv.y + wr[2]*xv.z + wr[3]*xv.w;
        #pragma unroll
        for (int d = 16; d > 0; d >>= 1) s += __shfl_xor_sync(0xffffffffu, s, d);
        if (lane < 9) {
            if (j == 2*lane)     dy = s;
            if (j == 2*lane + 1) dx = s;
        }
    }
    if (lane < 9) {
        int k = lane;
        dy += __ldg(&offb[2*k]);
        dx += __ldg(&offb[2*k+1]);
        float py = (float)(ho*2 - 1 + k/3) + dy;
        float px = (float)(wo*2 - 1 + k%3) + dx;
        float fy = floorf(py), fx = floorf(px);
        int y0 = (int)fy, x0 = (int)fx;
        g_params[(size_t)gw*KK9 + k] =
            make_float4(__int_as_float(y0), __int_as_float(x0), py - fy, px - fx);
    }
}

// ---------------- K2: main deformable conv ----------------
// 800 blocks: (b, 32-position tile). 256 threads.
// Gather: thread = (c4 group of 4 channels, position); float4 corner loads.
// GEMM:   thread = (o-pair, 16-pos subtile); 2x16 register tile, f32x2 FMAs.
__global__ __launch_bounds__(256, 3) void k_main(const float* __restrict__ deform_b) {
    int bid = blockIdx.x;
    int b   = bid / (NP/TPm);
    int p0  = (bid % (NP/TPm)) * TPm;
    int tid = threadIdx.x;

    __shared__ __align__(16) float4 sp[TPm*KK9];      // 288 taps, 4.6 KB
    __shared__ __align__(16) float  ssamp[CCm*KK9*PS];// 288 rows x 36, 41.5 KB

    for (int i = tid; i < TPm*KK9; i += 256)
        sp[i] = g_params[((size_t)b*NP + p0)*KK9 + i];

    unsigned long long a0[8], a1[8];
    #pragma unroll
    for (int i = 0; i < 8; i++) { a0[i] = 0ULL; a1[i] = 0ULL; }

    const float* xb = &g_xT[(size_t)b*HH*WW*CIN];
    int c4 = tid & 7;          // gather: 4-channel group within chunk
    int gp = tid >> 3;         // gather: position 0..31
    int o2 = tid & 127;        // gemm: output channel pair index
    int pt = tid >> 7;         // gemm: position subtile (0/1)

    __syncthreads();

    #pragma unroll 1
    for (int ch = 0; ch < CIN/CCm; ch++) {
        // ---- gather 32 channels x 288 (p,k) taps ----
        int cbase = ch*CCm + 4*c4;
        #pragma unroll 3
        for (int k = 0; k < KK9; k++) {
            float4 pr = sp[gp*KK9 + k];
            int y0 = __float_as_int(pr.x);
            int x0 = __float_as_int(pr.y);
            float wy1 = pr.z, wx1 = pr.w;
            float wy0 = 1.f - wy1, wx0 = 1.f - wx1;
            int y1 = y0 + 1, x1 = x0 + 1;
            bool vy0 = ((unsigned)y0 < (unsigned)HH);
            bool vy1 = ((unsigned)y1 < (unsigned)HH);
            bool vx0 = ((unsigned)x0 < (unsigned)WW);
            bool vx1 = ((unsigned)x1 < (unsigned)WW);
            int yc0 = min(max(y0, 0), HH-1), yc1 = min(max(y1, 0), HH-1);
            int xc0 = min(max(x0, 0), WW-1), xc1 = min(max(x1, 0), WW-1);
            const float4 z4 = make_float4(0.f,0.f,0.f,0.f);
            float4 g00 = (vy0 && vx0) ? *(const float4*)(xb + ((size_t)yc0*WW + xc0)*CIN + cbase) : z4;
            float4 g01 = (vy0 && vx1) ? *(const float4*)(xb + ((size_t)yc0*WW + xc1)*CIN + cbase) : z4;
            float4 g10 = (vy1 && vx0) ? *(const float4*)(xb + ((size_t)yc1*WW + xc0)*CIN + cbase) : z4;
            float4 g11 = (vy1 && vx1) ? *(const float4*)(xb + ((size_t)yc1*WW + xc1)*CIN + cbase) : z4;
            float4 v;
            v.x = wy0*(wx0*g00.x + wx1*g01.x) + wy1*(wx0*g10.x + wx1*g11.x);
            v.y = wy0*(wx0*g00.y + wx1*g01.y) + wy1*(wx0*g10.y + wx1*g11.y);
            v.z = wy0*(wx0*g00.z + wx1*g01.z) + wy1*(wx0*g10.z + wx1*g11.z);
            v.w = wy0*(wx0*g00.w + wx1*g01.w) + wy1*(wx0*g10.w + wx1*g11.w);
            int rb = (4*c4)*KK9 + k;               // row of channel 4*c4, tap k
            ssamp[(rb + 0*KK9)*PS + gp] = v.x;
            ssamp[(rb + 1*KK9)*PS + gp] = v.y;
            ssamp[(rb + 2*KK9)*PS + gp] = v.z;
            ssamp[(rb + 3*KK9)*PS + gp] = v.w;
        }
        __syncthreads();

        // ---- GEMM fragment: rows = 288 (c,k) x (2 o x 16 p) per thread ----
        const float* wp = &g_wT[(size_t)ch*(CCm*KK9)*COUT + 2*o2];
        const float* sbase = &ssamp[pt*16];
        #pragma unroll 4
        for (int r = 0; r < CCm*KK9; r++) {
            float2 w2 = *(const float2*)(wp + (size_t)r*COUT);
            unsigned long long w0 = pk2(w2.x, w2.x);
            unsigned long long w1 = pk2(w2.y, w2.y);
            const ulonglong2* s2 = (const ulonglong2*)(sbase + r*PS);
            ulonglong2 q0 = s2[0], q1 = s2[1];
            fma2(a0[0], w0, q0.x); fma2(a1[0], w1, q0.x);
            fma2(a0[1], w0, q0.y); fma2(a1[1], w1, q0.y);
            fma2(a0[2], w0, q1.x); fma2(a1[2], w1, q1.x);
            fma2(a0[3], w0, q1.y); fma2(a1[3], w1, q1.y);
            ulonglong2 q2 = s2[2], q3 = s2[3];
            fma2(a0[4], w0, q2.x); fma2(a1[4], w1, q2.x);
            fma2(a0[5], w0, q2.y); fma2(a1[5], w1, q2.y);
            fma2(a0[6], w0, q3.x); fma2(a1[6], w1, q3.x);
            fma2(a0[7], w0, q3.y); fma2(a1[7], w1, q3.y);
        }
        __syncthreads();
    }

    // ---- epilogue: bias + store (2 o x 16 consecutive positions) ----
    float2 bias = *(const float2*)(deform_b + 2*o2);
    float r0[16], r1[16];
    #pragma unroll
    for (int i = 0; i < 8; i++) {
        float lo, hi;
        upk2(a0[i], lo, hi); r0[2*i] = lo + bias.x; r0[2*i+1] = hi + bias.x;
        upk2(a1[i], lo, hi); r1[2*i] = lo + bias.y; r1[2*i+1] = hi + bias.y;
    }
    int pbase = p0 + pt*16;
    float4* out0 = (float4*)&g_pre[((size_t)(b*COUT + 2*o2  ))*NP + pbase];
    float4* out1 = (float4*)&g_pre[((size_t)(b*COUT + 2*o2+1))*NP + pbase];
    #pragma unroll
    for (int i = 0; i < 4; i++) {
        out0[i] = make_float4(r0[4*i], r0[4*i+1], r0[4*i+2], r0[4*i+3]);
        out1[i] = make_float4(r1[4*i], r1[4*i+1], r1[4*i+2], r1[4*i+3]);
    }
}

// ---------------- K3: BN statistics (deterministic two-pass) ----------------
__global__ void k_bnstats(const float* __restrict__ gamma, const float* __restrict__ beta) {
    int o = blockIdx.x;
    int tid = threadIdx.x;
    double s = 0.0, s2 = 0.0;
    for (int b = 0; b < BB; b++) {
        const float* r = &g_pre[((size_t)(b*COUT + o))*NP];
        for (int i = tid; i < NP; i += 256) {
            double v = (double)r[i];
            s  += v;
            s2 += v*v;
        }
    }
    __shared__ double sh[256], sh2[256];
    sh[tid] = s; sh2[tid] = s2;
    __syncthreads();
    for (int d = 128; d > 0; d >>= 1) {
        if (tid < d) { sh[tid] += sh[tid+d]; sh2[tid] += sh2[tid+d]; }
        __syncthreads();
    }
    if (tid == 0) {
        const double N = (double)(BB*NP);
        double mean = sh[0] / N;
        double var  = sh2[0] / N - mean*mean;
        double inv  = 1.0 / sqrt(var + 1e-5);
        float scale = (float)((double)gamma[o] * inv);
        float shift = (float)((double)beta[o] - mean * (double)scale);
        g_bn[2*o]   = scale;
        g_bn[2*o+1] = shift;
    }
}

// ---------------- K4: fused BN + SiLU ----------------
__global__ void k_act(float* __restrict__ out) {
    int i = blockIdx.x*256 + threadIdx.x;      // float4 index
    const int NV = BB*COUT*NP/4;
    if (i >= NV) return;
    int e = i*4;
    int o = (e / NP) & (COUT-1);
    float sc = g_bn[2*o], sh = g_bn[2*o+1];
    float4 v = ((const float4*)g_pre)[i];
    float y0 = v.x*sc + sh;
    float y1 = v.y*sc + sh;
    float y2 = v.z*sc + sh;
    float y3 = v.w*sc + sh;
    v.x = y0 / (1.f + __expf(-y0));
    v.y = y1 / (1.f + __expf(-y1));
    v.z = y2 / (1.f + __expf(-y2));
    v.w = y3 / (1.f + __expf(-y3));
    ((float4*)out)[i] = v;
}

// ---------------- launch ----------------
extern "C" void kernel_launch(void* const* d_in, const int* in_sizes, int n_in,
                              void* d_out, int out_size) {
    const float* x        = (const float*)d_in[0];
    const float* offset_w = (const float*)d_in[1];
    const float* offset_b = (const float*)d_in[2];
    const float* deform_w = (const float*)d_in[3];
    const float* deform_b = (const float*)d_in[4];
    const float* bn_gamma = (const float*)d_in[5];
    const float* bn_beta  = (const float*)d_in[6];
    float* out = (float*)d_out;

    k_transpose<<<BB*HH, 256>>>(x);
    k_wt<<<(RED*COUT + 255)/256, 256>>>(deform_w);
    k_offsets<<<(BB*NP*32 + 127)/128, 128>>>(offset_w, offset_b);
    k_main<<<BB*(NP/TPm), 256>>>(deform_b);
    k_bnstats<<<COUT, 256>>>(bn_gamma, bn_beta);
    k_act<<<(BB*COUT*NP/4 + 255)/256, 256>>>(out);
}